// round 5
// baseline (speedup 1.0000x reference)
#include <cuda_runtime.h>
#include <math.h>

// Problem constants (must match reference)
#define BB 16
#define HH 120
#define WW 160
#define DD 401              // int(8000/20)+1
#define WT 4                // w-tile per block
#define NT 384              // 12 warps -> 5 blocks/SM -> one full wave for 640 blocks
#define NPIX (HH * WT)      // 480 pixels per block
#define NV4 ((WT * DD) / 4) // 401 float4 in the block's output span
#define DEPTH_MAX 8000.0f
#define INV_BIN   (1.0f / 20.0f)
#define BIN_SIZE  20.0f
#define ZERO_EPS  1e-06f
#define SIG_EPS   (0.5f + 1e-08f)

// fp32 sparsity: the Gaussian underflows to exactly 0 unless |k*20 - d| < ~7.2;
// bins are 20 apart -> only the rounded-nearest bin k = round(d/20) can be
// nonzero. For valid d in (eps, 8000], k is in [0,400]: no clamp needed.
// (d > eps && d <= max) also rejects NaN/Inf.
//
// Structure: each block owns out[b, w0..w0+3, :] EXCLUSIVELY. It zeroes that
// span in GMEM up front (overlapped with the depth LDG), barriers
// (bar.sync == membar.cta: zeros ordered before this block's atomics at L2),
// then scatters with fire-and-forget global RED.E.ADD.F32. No smem, no
// second barrier, no post-sync 4.1MB store tail.

__global__ void __launch_bounds__(NT)
dim_hist_kernel(const float* __restrict__ depth, float* __restrict__ out)
{
    const int blk = blockIdx.x;              // 0 .. 639
    const int b   = blk / (WW / WT);
    const int w0  = (blk - b * (WW / WT)) * WT;
    const int tid = threadIdx.x;

    // ---- depth prefetch first: LDG latency overlaps the zeroing stores ----
    // pixel p -> h = p>>2, wi = p&3 ; consecutive tid -> consecutive w
    const float* dbase = depth + (size_t)b * HH * WW + w0;
    float d0 = -1.0f, d1 = -1.0f;
    d0 = __ldg(dbase + (tid >> 2) * WW + (tid & 3));            // tid < 480 always
    {
        int p2 = tid + NT;                                       // 384..767
        if (p2 < NPIX) d1 = __ldg(dbase + (p2 >> 2) * WW + (p2 & 3));
    }

    // ---- zero this block's private output span: 401 STG.128 ----
    float* ospan = out + ((size_t)b * WW + w0) * DD;             // 16B-aligned
    float4* o4 = (float4*)ospan;
    const float4 z4 = make_float4(0.f, 0.f, 0.f, 0.f);
    if (tid < NV4) o4[tid] = z4;
    if (tid + NT < NV4) o4[tid + NT] = z4;

    __syncthreads();   // exec + membar.cta: zeros visible before our atomics

    const float inv_sig = 1.0f / SIG_EPS;                 // 1/(sigma+eps)
    const float norm    = 0.3989422804014327f * inv_sig;  // 1/((sigma+eps)*sqrt(2pi))

    // ---- scatter: one EX2 + at most one no-return global atomic per pixel ----
    if (d0 > ZERO_EPS && d0 <= DEPTH_MAX) {
        int k   = __float2int_rn(d0 * INV_BIN);           // nearest bin, [0,400]
        float z = ((float)k * BIN_SIZE - d0) * inv_sig;
        float g = __expf(-0.5f * z * z) * norm;
        if (g != 0.0f) atomicAdd(&ospan[(tid & 3) * DD + k], g);   // RED.E.ADD.F32
    }
    if (d1 > ZERO_EPS && d1 <= DEPTH_MAX) {
        int k   = __float2int_rn(d1 * INV_BIN);
        float z = ((float)k * BIN_SIZE - d1) * inv_sig;
        float g = __expf(-0.5f * z * z) * norm;
        if (g != 0.0f) atomicAdd(&ospan[((tid + NT) & 3) * DD + k], g);
    }
}

extern "C" void kernel_launch(void* const* d_in, const int* in_sizes, int n_in,
                              void* d_out, int out_size)
{
    const float* depth = (const float*)d_in[0];
    float* out = (float*)d_out;
    dim_hist_kernel<<<(BB * WW) / WT, NT>>>(depth, out);
}